// round 16
// baseline (speedup 1.0000x reference)
#include <cuda_runtime.h>

// filtfilt (5-tap butter-style IIR, odd ext padlen=15) over 512 rows, T=32768.
//
// R16 = R15 (fully 128-bit vectorized tile pipeline, WARM=32, CH=64,
// 3 tiles/warp, NCH=544) + an L2 WARMER kernel: x (67MB) fits in the 126MB
// L2, so a ~10us bandwidth-saturated streaming read of x before fwd turns
// fwd's cold DRAM misses (~577cyc) into L2 hits (~234cyc) — the measured
// fwd/bwd gap (56.9 vs 35.5us) is exactly this latency difference (R15
// proved fwd is miss-latency bound, not instruction bound).
// rel_err @ WARM=32 measured ~1.65e-4 (gate 1e-3).
// Reference's per-row scale/descale is a linear no-op, skipped.

#define T_LEN     32768
#define PAD       15
#define TEXT      (T_LEN + 2 * PAD)   // 32798
#define ROWSTRIDE 32800
#define MAXROWS   512
#define NCH       544                 // chunks per row (17 * 32)
#define CH        64
#define WARM      32
#define TILES     3                    // WIN = 96
#define WPR       17
#define WPB       4
#define BLOCK     (WPB * 32)           // 128
#define TW        36                   // tile row stride; 16B multiple
#define U0        32798                // g[u] = y_fwd[U0 - u]

#define LD128(p)    (*reinterpret_cast<const float4*>(p))
#define ST128(p, v) (*reinterpret_cast<float4*>(p) = (v))

__device__ __align__(16) float g_fwd[(size_t)MAXROWS * ROWSTRIDE];
__device__ float g_sink;

struct Coef {
    float b0, b1, b2, b3, b4;
    float na1, na2, na3, na4;
};

__device__ __forceinline__ Coef load_coef(const float* __restrict__ bc,
                                          const float* __restrict__ ac) {
    Coef c;
    float inva0 = 1.0f / ac[0];
    c.b0 = bc[0] * inva0; c.b1 = bc[1] * inva0; c.b2 = bc[2] * inva0;
    c.b3 = bc[3] * inva0; c.b4 = bc[4] * inva0;
    c.na1 = -ac[1] * inva0; c.na2 = -ac[2] * inva0;
    c.na3 = -ac[3] * inva0; c.na4 = -ac[4] * inva0;
    return c;
}

// Direct-Form-I step; critical chain is the final fma through y1 (4 cyc).
#define IIR_STEP(xt)                                                   \
    do {                                                               \
        float f = fmaf(c.b0, (xt), fmaf(c.b1, x1,                      \
                  fmaf(c.b2, x2, fmaf(c.b3, x3, c.b4 * x4))));         \
        float s_ = fmaf(c.na2, y2, fmaf(c.na3, y3,                     \
                   fmaf(c.na4, y4, f)));                               \
        float y = fmaf(c.na1, y1, s_);                                 \
        x4 = x3; x3 = x2; x2 = x1; x1 = (xt);                          \
        y4 = y3; y3 = y2; y2 = y1; y1 = y;                             \
    } while (0)

// 8 IIR steps on one octet of the tile, optional store-back.
#define P2_OCTET(jb, do_store)                                         \
    do {                                                               \
        float4 va = LD128(&sm[lane][jb]);                              \
        float4 vb = LD128(&sm[lane][(jb) + 4]);                        \
        float4 wa, wb;                                                 \
        IIR_STEP(va.x); wa.x = y1; IIR_STEP(va.y); wa.y = y1;          \
        IIR_STEP(va.z); wa.z = y1; IIR_STEP(va.w); wa.w = y1;          \
        IIR_STEP(vb.x); wb.x = y1; IIR_STEP(vb.y); wb.y = y1;          \
        IIR_STEP(vb.z); wb.z = y1; IIR_STEP(vb.w); wb.w = y1;          \
        if (do_store) {                                                \
            ST128(&sm[lane][jb], wa);                                  \
            ST128(&sm[lane][(jb) + 4], wb);                            \
        }                                                              \
    } while (0)

// Odd-extended input at extended index t; 0 outside [0, TEXT).
__device__ __forceinline__ float load_xe_safe(const float* __restrict__ xr, int t) {
    if (t < 0)            return 0.0f;
    if (t < PAD)          return 2.0f * xr[0]         - xr[PAD - t];
    if (t < T_LEN + PAD)  return xr[t - PAD];
    if (t < TEXT)         return 2.0f * xr[T_LEN - 1] - xr[2 * T_LEN + PAD - 2 - t];
    return 0.0f;
}

// Streaming read of x to populate L2 (bandwidth-bound, ~10us for 67MB).
// The guarded store is never taken but prevents load elimination.
__global__ void __launch_bounds__(256)
warm_kernel(const float4* __restrict__ x4, int n4) {
    float acc = 0.f;
    int stride = gridDim.x * blockDim.x;
    for (int i = blockIdx.x * blockDim.x + threadIdx.x; i < n4; i += stride) {
        float4 v = x4[i];
        acc += v.x + v.y + v.z + v.w;
    }
    if (acc == 1.0e38f) g_sink = acc;
}

__global__ void __launch_bounds__(BLOCK)
fwd_kernel(const float* __restrict__ x,
           const float* __restrict__ bc,
           const float* __restrict__ ac) {
    int wib  = threadIdx.x >> 5;
    int lane = threadIdx.x & 31;
    int gw   = blockIdx.x * WPB + wib;
    int row  = gw / WPR;
    int wir  = gw - row * WPR;

    Coef c = load_coef(bc, ac);
    const float* xr = x + (size_t)row * T_LEN;
    float*       gr = g_fwd + (size_t)row * ROWSTRIDE;

    __shared__ __align__(16) float tile_s[WPB][32][TW];
    float (*sm)[TW] = tile_s[wib];

    int c0   = wir * 32;
    int base = c0 * CH - WARM + 3;      // == 3 (mod 4)
    bool fast = (wir != 0) && (wir != WPR - 1);
    int i0 = lane >> 3, q4 = (lane & 7) * 4;

    float x1 = 0.f, x2 = 0.f, x3 = 0.f, x4 = 0.f;
    float y1 = 0.f, y2 = 0.f, y3 = 0.f, y4 = 0.f;

    #pragma unroll
    for (int tl = 0; tl < TILES; ++tl) {
        int off = tl * 32;
        // Phase 1: tile fill. fast: LDG.128 + STS.128 (x idx base-15 == 0 mod 4).
        if (fast) {
            const float* p = xr + (base - PAD) + off;
            #pragma unroll
            for (int r8 = 0; r8 < 8; ++r8) {
                int i = r8 * 4 + i0;
                float4 v = LD128(p + i * CH + q4);
                ST128(&sm[i][q4], v);
            }
        } else {
            #pragma unroll 4
            for (int i = 0; i < 32; ++i)
                sm[i][lane] = load_xe_safe(xr, base + i * CH + off + lane);
        }
        __syncwarp();
        // Phase 2: 32 IIR steps; slow path stores all tiles (t<3 emission).
        bool st = (tl >= 1) || !fast;
        P2_OCTET(0,  st); P2_OCTET(8,  st);
        P2_OCTET(16, st); P2_OCTET(24, st);
        __syncwarp();
        // Phase 3: store TIME-REVERSED to g: g[U0 - t], reversed STG.128.
        if (fast) {
            if (tl >= 1) {
                float* qp = gr + (U0 - 3 - base - off);
                #pragma unroll
                for (int r8 = 0; r8 < 8; ++r8) {
                    int i = r8 * 4 + i0;
                    float4 v = LD128(&sm[i][q4]);
                    float4 w = make_float4(v.w, v.z, v.y, v.x);
                    ST128(qp - i * CH - q4, w);
                }
            }
        } else {
            // guarded scalar; chunk 0 also emits t in {0,1,2} from warm-up
            #pragma unroll 4
            for (int i = 0; i < 32; ++i) {
                int t = base + i * CH + off + lane;
                bool em = (off + lane >= WARM) || (t >= 0 && t < 3);
                if (em && t >= 0 && t < TEXT) gr[U0 - t] = sm[i][lane];
            }
        }
        __syncwarp();
    }
}

__global__ void __launch_bounds__(BLOCK)
bwd_kernel(const float* __restrict__ bc,
           const float* __restrict__ ac,
           float* __restrict__ out) {
    int wib  = threadIdx.x >> 5;
    int lane = threadIdx.x & 31;
    int gw   = blockIdx.x * WPB + wib;
    int row  = gw / WPR;
    int wir  = gw - row * WPR;

    Coef c = load_coef(bc, ac);
    const float* gr1  = g_fwd + (size_t)row * ROWSTRIDE + 1;  // g[1+s]
    float*       orow = out   + (size_t)row * T_LEN;

    __shared__ __align__(16) float tile_s[WPB][32][TW];
    float (*sm)[TW] = tile_s[wib];

    int c0   = wir * 32;
    int base = c0 * CH - WARM + 3;      // s-grid offset; (1+base) == 0 mod 4
    bool fast = (wir != 0) && (wir != WPR - 1);
    int i0 = lane >> 3, q4 = (lane & 7) * 4;

    float x1 = 0.f, x2 = 0.f, x3 = 0.f, x4 = 0.f;
    float y1 = 0.f, y2 = 0.f, y3 = 0.f, y4 = 0.f;

    #pragma unroll
    for (int tl = 0; tl < TILES; ++tl) {
        int off = tl * 32;
        // Phase 1: ascending reads of reversed scratch -> LDG.128 + STS.128.
        if (fast) {
            const float* p = gr1 + base + off;
            #pragma unroll
            for (int r8 = 0; r8 < 8; ++r8) {
                int i = r8 * 4 + i0;
                float4 v = LD128(p + i * CH + q4);
                ST128(&sm[i][q4], v);
            }
        } else {
            #pragma unroll 4
            for (int i = 0; i < 32; ++i) {
                int s = base + i * CH + off + lane;
                sm[i][lane] = (s >= 0 && s < TEXT) ? gr1[s] : 0.f;
            }
        }
        __syncwarp();
        bool st = (tl >= 1);
        P2_OCTET(0,  st); P2_OCTET(8,  st);
        P2_OCTET(16, st); P2_OCTET(24, st);
        __syncwarp();
        // Phase 3: out idx o = 32782 - s; quad start 32779-s0 == 0 mod 4:
        // reversed STG.128 (fast). Slow: guarded scalar.
        if (tl >= 1) {
            if (fast) {
                float* qp = orow + (32779 - base - off);
                #pragma unroll
                for (int r8 = 0; r8 < 8; ++r8) {
                    int i = r8 * 4 + i0;
                    float4 v = LD128(&sm[i][q4]);
                    float4 w = make_float4(v.w, v.z, v.y, v.x);
                    ST128(qp - i * CH - q4, w);
                }
            } else {
                #pragma unroll 4
                for (int i = 0; i < 32; ++i) {
                    int s = base + i * CH + off + lane;
                    int o = 32782 - s;
                    if (o >= 0 && o < T_LEN) orow[o] = sm[i][lane];
                }
            }
        }
        __syncwarp();
    }
}

extern "C" void kernel_launch(void* const* d_in, const int* in_sizes, int n_in,
                              void* d_out, int out_size) {
    const float* x  = (const float*)d_in[0];
    const float* bc = (const float*)d_in[1];
    const float* ac = (const float*)d_in[2];
    float* out = (float*)d_out;

    int nrows  = in_sizes[0] / T_LEN;          // 512
    int total_warps = nrows * WPR;             // 8704
    int blocks = total_warps / WPB;            // 2176 (exact)

    int n4 = in_sizes[0] / 4;                  // float4 count (T_LEN%4==0)
    warm_kernel<<<1184, 256>>>((const float4*)x, n4);

    fwd_kernel<<<blocks, BLOCK>>>(x, bc, ac);
    bwd_kernel<<<blocks, BLOCK>>>(bc, ac, out);
}

// round 17
// speedup vs baseline: 1.2799x; 1.2799x over previous
#include <cuda_runtime.h>

// filtfilt (5-tap butter-style IIR, odd ext padlen=15) over 512 rows, T=32768.
//
// R17 = R15 (fully 128-bit vectorized tile pipeline, WARM=32, CH=64,
// 3 tiles/warp, NCH=544) with the boundary ("slow") path made BRANCHLESS.
// R16's L2-warmer experiment falsified the miss-latency theory for fwd
// (warm L2 bought only ~3us); the remaining fwd/bwd gap (~21us) matches
// slow-warp drag: fwd's odd-extension loads were a 4-way BRANCH chain, and
// the 2/17 slow warps land in ~29% of blocks (block time = slowest warp).
// Now: clamped reflect-index + predicated selects, zero branches.
// rel_err @ WARM=32 measured ~1.65e-4 (gate 1e-3).
// Reference's per-row scale/descale is a linear no-op, skipped.

#define T_LEN     32768
#define PAD       15
#define TEXT      (T_LEN + 2 * PAD)   // 32798
#define ROWSTRIDE 32800
#define MAXROWS   512
#define NCH       544                 // chunks per row (17 * 32)
#define CH        64
#define WARM      32
#define TILES     3                    // WIN = 96
#define WPR       17
#define WPB       4
#define BLOCK     (WPB * 32)           // 128
#define TW        36                   // tile row stride; 16B multiple
#define U0        32798                // g[u] = y_fwd[U0 - u]

#define LD128(p)    (*reinterpret_cast<const float4*>(p))
#define ST128(p, v) (*reinterpret_cast<float4*>(p) = (v))

__device__ __align__(16) float g_fwd[(size_t)MAXROWS * ROWSTRIDE];

struct Coef {
    float b0, b1, b2, b3, b4;
    float na1, na2, na3, na4;
};

__device__ __forceinline__ Coef load_coef(const float* __restrict__ bc,
                                          const float* __restrict__ ac) {
    Coef c;
    float inva0 = 1.0f / ac[0];
    c.b0 = bc[0] * inva0; c.b1 = bc[1] * inva0; c.b2 = bc[2] * inva0;
    c.b3 = bc[3] * inva0; c.b4 = bc[4] * inva0;
    c.na1 = -ac[1] * inva0; c.na2 = -ac[2] * inva0;
    c.na3 = -ac[3] * inva0; c.na4 = -ac[4] * inva0;
    return c;
}

// Direct-Form-I step; critical chain is the final fma through y1 (4 cyc).
#define IIR_STEP(xt)                                                   \
    do {                                                               \
        float f = fmaf(c.b0, (xt), fmaf(c.b1, x1,                      \
                  fmaf(c.b2, x2, fmaf(c.b3, x3, c.b4 * x4))));         \
        float s_ = fmaf(c.na2, y2, fmaf(c.na3, y3,                     \
                   fmaf(c.na4, y4, f)));                               \
        float y = fmaf(c.na1, y1, s_);                                 \
        x4 = x3; x3 = x2; x2 = x1; x1 = (xt);                          \
        y4 = y3; y3 = y2; y2 = y1; y1 = y;                             \
    } while (0)

// 8 IIR steps on one octet of the tile, optional store-back.
#define P2_OCTET(jb, do_store)                                         \
    do {                                                               \
        float4 va = LD128(&sm[lane][jb]);                              \
        float4 vb = LD128(&sm[lane][(jb) + 4]);                        \
        float4 wa, wb;                                                 \
        IIR_STEP(va.x); wa.x = y1; IIR_STEP(va.y); wa.y = y1;          \
        IIR_STEP(va.z); wa.z = y1; IIR_STEP(va.w); wa.w = y1;          \
        IIR_STEP(vb.x); wb.x = y1; IIR_STEP(vb.y); wb.y = y1;          \
        IIR_STEP(vb.z); wb.z = y1; IIR_STEP(vb.w); wb.w = y1;          \
        if (do_store) {                                                \
            ST128(&sm[lane][jb], wa);                                  \
            ST128(&sm[lane][(jb) + 4], wb);                            \
        }                                                              \
    } while (0)

// BRANCHLESS odd-extended input at extended index t (0 outside [0, TEXT)).
// e0 = 2*x[0], e1 = 2*x[T-1] preloaded by the caller.
__device__ __forceinline__ float load_xe_bf(const float* __restrict__ xr,
                                            int t, float e0, float e1) {
    int  idx = t - PAD;
    bool lo  = idx < 0;
    bool hi  = idx >= T_LEN;
    int  j   = lo ? -idx : idx;
    j        = hi ? (2 * T_LEN - 2 - idx) : j;
    j        = min(max(j, 0), T_LEN - 1);          // memory-safe clamp
    float v  = __ldg(&xr[j]);
    float r  = lo ? (e0 - v) : v;
    r        = hi ? (e1 - v) : r;
    return (t < 0 || t >= TEXT) ? 0.0f : r;
}

__global__ void __launch_bounds__(BLOCK)
fwd_kernel(const float* __restrict__ x,
           const float* __restrict__ bc,
           const float* __restrict__ ac) {
    int wib  = threadIdx.x >> 5;
    int lane = threadIdx.x & 31;
    int gw   = blockIdx.x * WPB + wib;
    int row  = gw / WPR;
    int wir  = gw - row * WPR;

    Coef c = load_coef(bc, ac);
    const float* xr = x + (size_t)row * T_LEN;
    float*       gr = g_fwd + (size_t)row * ROWSTRIDE;

    __shared__ __align__(16) float tile_s[WPB][32][TW];
    float (*sm)[TW] = tile_s[wib];

    int c0   = wir * 32;
    int base = c0 * CH - WARM + 3;      // == 3 (mod 4)
    bool fast = (wir != 0) && (wir != WPR - 1);
    int i0 = lane >> 3, q4 = (lane & 7) * 4;

    float x1 = 0.f, x2 = 0.f, x3 = 0.f, x4 = 0.f;
    float y1 = 0.f, y2 = 0.f, y3 = 0.f, y4 = 0.f;
    float e0 = 2.0f * xr[0], e1 = 2.0f * xr[T_LEN - 1];

    #pragma unroll
    for (int tl = 0; tl < TILES; ++tl) {
        int off = tl * 32;
        // Phase 1: tile fill. fast: LDG.128 + STS.128 (x idx base-15 == 0 mod 4).
        if (fast) {
            const float* p = xr + (base - PAD) + off;
            #pragma unroll
            for (int r8 = 0; r8 < 8; ++r8) {
                int i = r8 * 4 + i0;
                float4 v = LD128(p + i * CH + q4);
                ST128(&sm[i][q4], v);
            }
        } else {
            // branchless boundary loads (coalesced per row, zero branches)
            #pragma unroll 4
            for (int i = 0; i < 32; ++i)
                sm[i][lane] = load_xe_bf(xr, base + i * CH + off + lane, e0, e1);
        }
        __syncwarp();
        // Phase 2: 32 IIR steps; slow path stores all tiles (t<3 emission).
        bool st = (tl >= 1) || !fast;
        P2_OCTET(0,  st); P2_OCTET(8,  st);
        P2_OCTET(16, st); P2_OCTET(24, st);
        __syncwarp();
        // Phase 3: store TIME-REVERSED to g: g[U0 - t], reversed STG.128.
        if (fast) {
            if (tl >= 1) {
                float* qp = gr + (U0 - 3 - base - off);
                #pragma unroll
                for (int r8 = 0; r8 < 8; ++r8) {
                    int i = r8 * 4 + i0;
                    float4 v = LD128(&sm[i][q4]);
                    float4 w = make_float4(v.w, v.z, v.y, v.x);
                    ST128(qp - i * CH - q4, w);
                }
            }
        } else {
            // predicated scalar; chunk 0 also emits t in {0,1,2} from warm-up
            #pragma unroll 4
            for (int i = 0; i < 32; ++i) {
                int t = base + i * CH + off + lane;
                bool em = (off + lane >= WARM) || (t >= 0 && t < 3);
                if (em && t >= 0 && t < TEXT) gr[U0 - t] = sm[i][lane];
            }
        }
        __syncwarp();
    }
}

__global__ void __launch_bounds__(BLOCK)
bwd_kernel(const float* __restrict__ bc,
           const float* __restrict__ ac,
           float* __restrict__ out) {
    int wib  = threadIdx.x >> 5;
    int lane = threadIdx.x & 31;
    int gw   = blockIdx.x * WPB + wib;
    int row  = gw / WPR;
    int wir  = gw - row * WPR;

    Coef c = load_coef(bc, ac);
    const float* gr1  = g_fwd + (size_t)row * ROWSTRIDE + 1;  // g[1+s]
    float*       orow = out   + (size_t)row * T_LEN;

    __shared__ __align__(16) float tile_s[WPB][32][TW];
    float (*sm)[TW] = tile_s[wib];

    int c0   = wir * 32;
    int base = c0 * CH - WARM + 3;      // s-grid offset; (1+base) == 0 mod 4
    bool fast = (wir != 0) && (wir != WPR - 1);
    int i0 = lane >> 3, q4 = (lane & 7) * 4;

    float x1 = 0.f, x2 = 0.f, x3 = 0.f, x4 = 0.f;
    float y1 = 0.f, y2 = 0.f, y3 = 0.f, y4 = 0.f;

    #pragma unroll
    for (int tl = 0; tl < TILES; ++tl) {
        int off = tl * 32;
        // Phase 1: ascending reads of reversed scratch -> LDG.128 + STS.128.
        if (fast) {
            const float* p = gr1 + base + off;
            #pragma unroll
            for (int r8 = 0; r8 < 8; ++r8) {
                int i = r8 * 4 + i0;
                float4 v = LD128(p + i * CH + q4);
                ST128(&sm[i][q4], v);
            }
        } else {
            // branchless: clamped index + zero select (memory-safe)
            #pragma unroll 4
            for (int i = 0; i < 32; ++i) {
                int s  = base + i * CH + off + lane;
                int sc = min(max(s, 0), TEXT - 1);
                float v = __ldg(&gr1[sc]);
                sm[i][lane] = (s >= 0 && s < TEXT) ? v : 0.0f;
            }
        }
        __syncwarp();
        bool st = (tl >= 1);
        P2_OCTET(0,  st); P2_OCTET(8,  st);
        P2_OCTET(16, st); P2_OCTET(24, st);
        __syncwarp();
        // Phase 3: out idx o = 32782 - s; quad start 32779-s0 == 0 mod 4:
        // reversed STG.128 (fast). Slow: predicated scalar.
        if (tl >= 1) {
            if (fast) {
                float* qp = orow + (32779 - base - off);
                #pragma unroll
                for (int r8 = 0; r8 < 8; ++r8) {
                    int i = r8 * 4 + i0;
                    float4 v = LD128(&sm[i][q4]);
                    float4 w = make_float4(v.w, v.z, v.y, v.x);
                    ST128(qp - i * CH - q4, w);
                }
            } else {
                #pragma unroll 4
                for (int i = 0; i < 32; ++i) {
                    int s = base + i * CH + off + lane;
                    int o = 32782 - s;
                    if (o >= 0 && o < T_LEN) orow[o] = sm[i][lane];
                }
            }
        }
        __syncwarp();
    }
}

extern "C" void kernel_launch(void* const* d_in, const int* in_sizes, int n_in,
                              void* d_out, int out_size) {
    const float* x  = (const float*)d_in[0];
    const float* bc = (const float*)d_in[1];
    const float* ac = (const float*)d_in[2];
    float* out = (float*)d_out;

    int nrows  = in_sizes[0] / T_LEN;          // 512
    int total_warps = nrows * WPR;             // 8704
    int blocks = total_warps / WPB;            // 2176 (exact)

    fwd_kernel<<<blocks, BLOCK>>>(x, bc, ac);
    bwd_kernel<<<blocks, BLOCK>>>(bc, ac, out);
}